// round 3
// baseline (speedup 1.0000x reference)
#include <cuda_runtime.h>
#include <math.h>

#define B_ 2
#define S_ 2048
#define D_ 1024
#define H_ 16
#define DK_ 64
#define TD_ 3072          // 3*D
#define MROWS_ 4096       // B*S
#define QUARTER_ 16

// Scratch (device globals — no allocation allowed)
__device__ float g_qkv[B_ * S_ * TD_];   // [B,S,3D]
__device__ float g_att[B_ * S_ * D_];    // [B,S,D] attention output (pre-Wo)
__device__ float g_cos[S_ * QUARTER_];
__device__ float g_sin[S_ * QUARTER_];

// ---------------------------------------------------------------------------
// RoPE tables: ang[j] = (1e-4)^(j/15) for j<16 (rest of half-width is identity)
// Computed in double for accuracy at theta up to ~2047.
// ---------------------------------------------------------------------------
__global__ void rope_table_k() {
    int i = blockIdx.x * blockDim.x + threadIdx.x;
    if (i >= S_ * QUARTER_) return;
    int s = i / QUARTER_;
    int j = i % QUARTER_;
    double ang = pow(1.0e-4, (double)j / (double)(QUARTER_ - 1));
    double th = (double)s * ang;
    g_cos[i] = (float)cos(th);
    g_sin[i] = (float)sin(th);
}

// In-place partial RoPE on q and k slices of g_qkv.
// Pairs (j, j+32) within each head, j < 16 only (j in [16,32) is identity).
__global__ void rope_apply_k() {
    int idx = blockIdx.x * blockDim.x + threadIdx.x;
    if (idx >= B_ * S_ * 2 * H_ * QUARTER_) return;
    int j = idx % QUARTER_;  int t = idx / QUARTER_;
    int h = t % H_;          t /= H_;
    int qk = t & 1;          t >>= 1;
    int s = t % S_;
    int b = t / S_;
    size_t base = ((size_t)(b * S_ + s)) * TD_ + (size_t)qk * D_ + h * DK_;
    float c  = g_cos[s * QUARTER_ + j];
    float sn = g_sin[s * QUARTER_ + j];
    float x1 = g_qkv[base + j];
    float x2 = g_qkv[base + j + 32];
    g_qkv[base + j]      = x1 * c - x2 * sn;
    g_qkv[base + j + 32] = x1 * sn + x2 * c;
}

// ---------------------------------------------------------------------------
// SGEMM: C[m][n] = sum_k A[m][k] * W[n][k]   (both operands K-major row-major)
// 128x128 block tile, BK=16, 256 threads, 8x8 microtile.
// ---------------------------------------------------------------------------
__global__ __launch_bounds__(256)
void sgemm_nt(const float* __restrict__ A, const float* __restrict__ W,
              float* __restrict__ C, int M, int N, int K) {
    __shared__ float As[16][132];
    __shared__ float Bs[16][132];
    int tid = threadIdx.x;
    int tx = tid & 15, ty = tid >> 4;
    int bm = blockIdx.y << 7, bn = blockIdx.x << 7;
    int lr = tid >> 2;          // 0..63
    int lc = (tid & 3) << 2;    // 0,4,8,12

    const float* Ap = A + (size_t)(bm + lr) * K + lc;
    const float* Bp = W + (size_t)(bn + lr) * K + lc;

    float acc[8][8] = {{0.f}};

    for (int k0 = 0; k0 < K; k0 += 16) {
        float4 a0 = *(const float4*)(Ap + k0);
        float4 a1 = *(const float4*)(Ap + (size_t)64 * K + k0);
        float4 b0 = *(const float4*)(Bp + k0);
        float4 b1 = *(const float4*)(Bp + (size_t)64 * K + k0);
        __syncthreads();
        As[lc + 0][lr] = a0.x; As[lc + 1][lr] = a0.y;
        As[lc + 2][lr] = a0.z; As[lc + 3][lr] = a0.w;
        As[lc + 0][lr + 64] = a1.x; As[lc + 1][lr + 64] = a1.y;
        As[lc + 2][lr + 64] = a1.z; As[lc + 3][lr + 64] = a1.w;
        Bs[lc + 0][lr] = b0.x; Bs[lc + 1][lr] = b0.y;
        Bs[lc + 2][lr] = b0.z; Bs[lc + 3][lr] = b0.w;
        Bs[lc + 0][lr + 64] = b1.x; Bs[lc + 1][lr + 64] = b1.y;
        Bs[lc + 2][lr + 64] = b1.z; Bs[lc + 3][lr + 64] = b1.w;
        __syncthreads();
        #pragma unroll
        for (int kk = 0; kk < 16; kk++) {
            float4 A0 = *(const float4*)&As[kk][ty << 2];
            float4 A1 = *(const float4*)&As[kk][64 + (ty << 2)];
            float4 B0 = *(const float4*)&Bs[kk][tx << 2];
            float4 B1 = *(const float4*)&Bs[kk][64 + (tx << 2)];
            float av[8] = {A0.x, A0.y, A0.z, A0.w, A1.x, A1.y, A1.z, A1.w};
            float bv[8] = {B0.x, B0.y, B0.z, B0.w, B1.x, B1.y, B1.z, B1.w};
            #pragma unroll
            for (int i = 0; i < 8; i++)
                #pragma unroll
                for (int j = 0; j < 8; j++)
                    acc[i][j] += av[i] * bv[j];
        }
    }

    #pragma unroll
    for (int i = 0; i < 8; i++) {
        int r = bm + ((i < 4) ? (ty << 2) + i : 64 + (ty << 2) + (i - 4));
        float* Cp = C + (size_t)r * N + bn;
        *(float4*)(Cp + (tx << 2)) =
            make_float4(acc[i][0], acc[i][1], acc[i][2], acc[i][3]);
        *(float4*)(Cp + 64 + (tx << 2)) =
            make_float4(acc[i][4], acc[i][5], acc[i][6], acc[i][7]);
    }
}

// ---------------------------------------------------------------------------
// Flash attention, fp32. One block per (qtile=64, h, b). 256 threads (16x16),
// 4x4 microtile. smem: sQ[d][r], sK[d][c] (reused as sP[c][r]), sV[c][d].
// Stride 68 keeps LDS.128 aligned and the bulk loads conflict-free.
// ---------------------------------------------------------------------------
#define AST 68
#define ATTN_SMEM (3 * 64 * AST * 4)

__global__ __launch_bounds__(256)
void attn_k() {
    extern __shared__ float sm[];
    float* sQ = sm;                 // [64][AST] d-major
    float* sK = sm + 64 * AST;      // [64][AST] d-major; reused as sP[c][r]
    float* sV = sm + 2 * 64 * AST;  // [64][AST] c-major

    int b = blockIdx.z, h = blockIdx.y, qt = blockIdx.x;
    int tid = threadIdx.x;
    int tx = tid & 15, ty = tid >> 4;
    int q0 = qt << 6;

    const float* qbase = g_qkv + (size_t)(b * S_) * TD_ + h * DK_;
    const float* kbase = qbase + D_;
    const float* vbase = qbase + 2 * D_;

    // Load Q transposed: sQ[d][r]
    {
        int d = tid & 63;
        int r0 = (tid >> 6) << 2;   // 0,4,8,12
        #pragma unroll
        for (int p = 0; p < 4; p++) {
            int r = p * 16 + r0;
            float v0 = qbase[(size_t)(q0 + r + 0) * TD_ + d];
            float v1 = qbase[(size_t)(q0 + r + 1) * TD_ + d];
            float v2 = qbase[(size_t)(q0 + r + 2) * TD_ + d];
            float v3 = qbase[(size_t)(q0 + r + 3) * TD_ + d];
            *(float4*)&sQ[d * AST + r] = make_float4(v0, v1, v2, v3);
        }
    }

    float o[4][4] = {{0.f}};
    float m_i[4], l_i[4];
    #pragma unroll
    for (int i = 0; i < 4; i++) { m_i[i] = -INFINITY; l_i[i] = 0.f; }

    for (int kt = 0; kt <= qt; kt++) {
        int k0 = kt << 6;
        __syncthreads();  // prev PV done reading sP/sV before overwrite
        // Load K transposed: sK[d][c]
        {
            int d = tid & 63;
            int c0 = (tid >> 6) << 2;
            #pragma unroll
            for (int p = 0; p < 4; p++) {
                int c = p * 16 + c0;
                float v0 = kbase[(size_t)(k0 + c + 0) * TD_ + d];
                float v1 = kbase[(size_t)(k0 + c + 1) * TD_ + d];
                float v2 = kbase[(size_t)(k0 + c + 2) * TD_ + d];
                float v3 = kbase[(size_t)(k0 + c + 3) * TD_ + d];
                *(float4*)&sK[d * AST + c] = make_float4(v0, v1, v2, v3);
            }
        }
        // Load V natural: sV[c][d]
        {
            int f4 = (tid & 15) << 2;
            int rr = tid >> 4;
            #pragma unroll
            for (int p = 0; p < 4; p++) {
                int c = p * 16 + rr;
                float4 v = *(const float4*)&vbase[(size_t)(k0 + c) * TD_ + f4];
                *(float4*)&sV[c * AST + f4] = v;
            }
        }
        __syncthreads();

        // S = Q K^T (4x4 per thread)
        float s[4][4] = {{0.f}};
        #pragma unroll 16
        for (int d = 0; d < 64; d++) {
            float4 qf = *(const float4*)&sQ[d * AST + (ty << 2)];
            float4 kf = *(const float4*)&sK[d * AST + (tx << 2)];
            float qa[4] = {qf.x, qf.y, qf.z, qf.w};
            float ka[4] = {kf.x, kf.y, kf.z, kf.w};
            #pragma unroll
            for (int i = 0; i < 4; i++)
                #pragma unroll
                for (int j = 0; j < 4; j++)
                    s[i][j] += qa[i] * ka[j];
        }

        // scale + causal mask (only diagonal tile needs masking)
        const float sc = 0.125f;  // 1/sqrt(64)
        if (kt == qt) {
            #pragma unroll
            for (int i = 0; i < 4; i++)
                #pragma unroll
                for (int j = 0; j < 4; j++) {
                    int cc = (tx << 2) + j, rr = (ty << 2) + i;
                    s[i][j] = (cc <= rr) ? s[i][j] * sc : -INFINITY;
                }
        } else {
            #pragma unroll
            for (int i = 0; i < 4; i++)
                #pragma unroll
                for (int j = 0; j < 4; j++) s[i][j] *= sc;
        }

        // online softmax (row reductions across the 16 tx lanes)
        #pragma unroll
        for (int i = 0; i < 4; i++) {
            float rmax = fmaxf(fmaxf(s[i][0], s[i][1]), fmaxf(s[i][2], s[i][3]));
            rmax = fmaxf(rmax, __shfl_xor_sync(0xffffffffu, rmax, 1));
            rmax = fmaxf(rmax, __shfl_xor_sync(0xffffffffu, rmax, 2));
            rmax = fmaxf(rmax, __shfl_xor_sync(0xffffffffu, rmax, 4));
            rmax = fmaxf(rmax, __shfl_xor_sync(0xffffffffu, rmax, 8));
            float nm = fmaxf(m_i[i], rmax);
            float corr = __expf(m_i[i] - nm);
            float ps = 0.f;
            #pragma unroll
            for (int j = 0; j < 4; j++) {
                float p = __expf(s[i][j] - nm);
                s[i][j] = p;
                ps += p;
            }
            ps += __shfl_xor_sync(0xffffffffu, ps, 1);
            ps += __shfl_xor_sync(0xffffffffu, ps, 2);
            ps += __shfl_xor_sync(0xffffffffu, ps, 4);
            ps += __shfl_xor_sync(0xffffffffu, ps, 8);
            l_i[i] = l_i[i] * corr + ps;
            m_i[i] = nm;
            #pragma unroll
            for (int j = 0; j < 4; j++) o[i][j] *= corr;
        }

        __syncthreads();  // everyone done reading sK before P overwrites it
        // write P transposed into sK storage: sP[c][r]
        #pragma unroll
        for (int j = 0; j < 4; j++) {
            *(float4*)&sK[((tx << 2) + j) * AST + (ty << 2)] =
                make_float4(s[0][j], s[1][j], s[2][j], s[3][j]);
        }
        __syncthreads();

        // O += P V
        #pragma unroll 16
        for (int c = 0; c < 64; c++) {
            float4 pf = *(const float4*)&sK[c * AST + (ty << 2)];
            float4 vf = *(const float4*)&sV[c * AST + (tx << 2)];
            float pa[4] = {pf.x, pf.y, pf.z, pf.w};
            float va[4] = {vf.x, vf.y, vf.z, vf.w};
            #pragma unroll
            for (int i = 0; i < 4; i++)
                #pragma unroll
                for (int j = 0; j < 4; j++)
                    o[i][j] += pa[i] * va[j];
        }
    }

    // epilogue: normalize and write [B,S,D] layout directly
    float* obase = g_att + (size_t)(b * S_) * D_ + h * DK_;
    #pragma unroll
    for (int i = 0; i < 4; i++) {
        float inv = 1.0f / l_i[i];
        *(float4*)&obase[(size_t)(q0 + (ty << 2) + i) * D_ + (tx << 2)] =
            make_float4(o[i][0] * inv, o[i][1] * inv, o[i][2] * inv, o[i][3] * inv);
    }
}

// ---------------------------------------------------------------------------
extern "C" void kernel_launch(void* const* d_in, const int* in_sizes, int n_in,
                              void* d_out, int out_size) {
    const float* x    = (const float*)d_in[0];
    const float* Wqkv = (const float*)d_in[1];
    const float* Wo   = (const float*)d_in[2];
    float* out = (float*)d_out;

    float *qkv_p, *att_p;
    cudaGetSymbolAddress((void**)&qkv_p, g_qkv);
    cudaGetSymbolAddress((void**)&att_p, g_att);

    cudaFuncSetAttribute(attn_k, cudaFuncAttributeMaxDynamicSharedMemorySize,
                         ATTN_SMEM);

    // 1. RoPE tables (independent)
    rope_table_k<<<(S_ * QUARTER_ + 255) / 256, 256>>>();
    // 2. QKV projection: [4096,1024] x [3072,1024]^T -> [4096,3072]
    sgemm_nt<<<dim3(TD_ / 128, MROWS_ / 128), 256>>>(x, Wqkv, qkv_p,
                                                     MROWS_, TD_, D_);
    // 3. RoPE in place on q,k
    rope_apply_k<<<(B_ * S_ * 2 * H_ * QUARTER_ + 255) / 256, 256>>>();
    // 4. causal attention -> g_att in [B,S,D] layout
    attn_k<<<dim3(S_ / 64, H_, B_), 256, ATTN_SMEM>>>();
    // 5. output projection: [4096,1024] x [1024,1024]^T -> d_out
    sgemm_nt<<<dim3(D_ / 128, MROWS_ / 128), 256>>>(att_p, Wo, out,
                                                    MROWS_, D_, D_);
}

// round 6
// speedup vs baseline: 1.3132x; 1.3132x over previous
#include <cuda_runtime.h>
#include <cuda_bf16.h>
#include <math.h>
#include <stdint.h>

#define B_ 2
#define S_ 2048
#define D_ 1024
#define H_ 16
#define DK_ 64
#define TD_ 3072          // 3*D
#define MROWS_ 4096       // B*S
#define QUARTER_ 16
#define GK_ 1024          // K dim of both projections

// ---------------------------------------------------------------------------
// Scratch (device globals — no allocation allowed)
// ---------------------------------------------------------------------------
__device__ float g_qkv[B_ * S_ * TD_];   // [B,S,3D] fp32 (attention reads this)
__device__ float g_att[B_ * S_ * D_];    // [B,S,D] attention output (pre-Wo)
__device__ float g_cos[S_ * QUARTER_];
__device__ float g_sin[S_ * QUARTER_];
// bf16 split-precision operand buffers
__device__ __nv_bfloat16 g_xh[MROWS_ * D_],  g_xl[MROWS_ * D_];
__device__ __nv_bfloat16 g_wqh[TD_ * D_],    g_wql[TD_ * D_];
__device__ __nv_bfloat16 g_woh[D_ * D_],     g_wol[D_ * D_];
__device__ __nv_bfloat16 g_ath[MROWS_ * D_], g_atl[MROWS_ * D_];

// ---------------------------------------------------------------------------
// RoPE tables + apply
// ---------------------------------------------------------------------------
__global__ void rope_table_k() {
    int i = blockIdx.x * blockDim.x + threadIdx.x;
    if (i >= S_ * QUARTER_) return;
    int s = i / QUARTER_;
    int j = i % QUARTER_;
    double ang = pow(1.0e-4, (double)j / (double)(QUARTER_ - 1));
    double th = (double)s * ang;
    g_cos[i] = (float)cos(th);
    g_sin[i] = (float)sin(th);
}

__global__ void rope_apply_k() {
    int idx = blockIdx.x * blockDim.x + threadIdx.x;
    if (idx >= B_ * S_ * 2 * H_ * QUARTER_) return;
    int j = idx % QUARTER_;  int t = idx / QUARTER_;
    int h = t % H_;          t /= H_;
    int qk = t & 1;          t >>= 1;
    int s = t % S_;
    int b = t / S_;
    size_t base = ((size_t)(b * S_ + s)) * TD_ + (size_t)qk * D_ + h * DK_;
    float c  = g_cos[s * QUARTER_ + j];
    float sn = g_sin[s * QUARTER_ + j];
    float x1 = g_qkv[base + j];
    float x2 = g_qkv[base + j + 32];
    g_qkv[base + j]      = x1 * c - x2 * sn;
    g_qkv[base + j + 32] = x1 * sn + x2 * c;
}

// ---------------------------------------------------------------------------
// fp32 -> (bf16 hi, bf16 lo) splitter. 4 elements per thread.
// ---------------------------------------------------------------------------
__global__ __launch_bounds__(256)
void split_k(const float* __restrict__ src, __nv_bfloat16* __restrict__ hi,
             __nv_bfloat16* __restrict__ lo, int n4) {
    int i = blockIdx.x * blockDim.x + threadIdx.x;
    if (i >= n4) return;
    float4 v = ((const float4*)src)[i];
    __nv_bfloat16 h0 = __float2bfloat16(v.x);
    __nv_bfloat16 h1 = __float2bfloat16(v.y);
    __nv_bfloat16 h2 = __float2bfloat16(v.z);
    __nv_bfloat16 h3 = __float2bfloat16(v.w);
    __nv_bfloat16 l0 = __float2bfloat16(v.x - __bfloat162float(h0));
    __nv_bfloat16 l1 = __float2bfloat16(v.y - __bfloat162float(h1));
    __nv_bfloat16 l2 = __float2bfloat16(v.z - __bfloat162float(h2));
    __nv_bfloat16 l3 = __float2bfloat16(v.w - __bfloat162float(h3));
    ((__nv_bfloat162*)hi)[2 * i + 0] = __nv_bfloat162(h0, h1);
    ((__nv_bfloat162*)hi)[2 * i + 1] = __nv_bfloat162(h2, h3);
    ((__nv_bfloat162*)lo)[2 * i + 0] = __nv_bfloat162(l0, l1);
    ((__nv_bfloat162*)lo)[2 * i + 1] = __nv_bfloat162(l2, l3);
}

// ---------------------------------------------------------------------------
// mma.sync split-bf16 GEMM (portable HMMA path — tcgen05 is unavailable in
// this build's compute_103 PTX target).
// C[m][n] = sum_k (Ah+Al)[m][k] * (Bh+Bl)[n][k], dropping Al*Bl.
// CTA 128x128, BK=32, 8 warps (warp tile 64x32), fp32 accum.
// ---------------------------------------------------------------------------
#define BK_ 32
#define ASTR_ 40                       // smem row stride in bf16 (20 banks)
#define TILE_ELEMS_ (128 * ASTR_)      // one operand tile in smem

#define MMA16816(d, a, b) \
    asm volatile( \
        "mma.sync.aligned.m16n8k16.row.col.f32.bf16.bf16.f32 " \
        "{%0,%1,%2,%3}, {%4,%5,%6,%7}, {%8,%9}, {%0,%1,%2,%3};" \
        : "+f"((d)[0]), "+f"((d)[1]), "+f"((d)[2]), "+f"((d)[3]) \
        : "r"((a)[0]), "r"((a)[1]), "r"((a)[2]), "r"((a)[3]), \
          "r"((b)[0]), "r"((b)[1]))

__device__ __forceinline__ void stage_load(
    uint4 st[8],
    const __nv_bfloat16* __restrict__ Ah, const __nv_bfloat16* __restrict__ Al,
    const __nv_bfloat16* __restrict__ Bh, const __nv_bfloat16* __restrict__ Bl,
    int bm, int bn, int kc, int tid) {
    #pragma unroll
    for (int u = 0; u < 8; u++) {
        int id = tid + (u << 8);
        int tile = id >> 9;        // 0..3  (512 ids per tile)
        int rem = id & 511;
        int row = rem >> 2;        // 0..127
        int seg = rem & 3;         // 16B segment -> 8 bf16
        const __nv_bfloat16* src;
        if (tile == 0)      src = Ah + (size_t)(bm + row) * GK_;
        else if (tile == 1) src = Al + (size_t)(bm + row) * GK_;
        else if (tile == 2) src = Bh + (size_t)(bn + row) * GK_;
        else                src = Bl + (size_t)(bn + row) * GK_;
        st[u] = *(const uint4*)(src + kc + seg * 8);
    }
}

__global__ __launch_bounds__(256, 1)
void gemm_mma(const __nv_bfloat16* __restrict__ Ah, const __nv_bfloat16* __restrict__ Al,
              const __nv_bfloat16* __restrict__ Bh, const __nv_bfloat16* __restrict__ Bl,
              float* __restrict__ C, int N) {
    __shared__ __nv_bfloat16 smem[4 * TILE_ELEMS_];  // Ah,Al,Bh,Bl tiles
    int tid = threadIdx.x;
    int lane = tid & 31, wid = tid >> 5;
    int warp_m = wid & 1;        // 0..1 -> m offset *64
    int warp_n = wid >> 1;       // 0..3 -> n offset *32
    int bm = blockIdx.y << 7, bn = blockIdx.x << 7;

    int g = lane >> 2;           // group id 0..7
    int tg2 = (lane & 3) << 1;   // 0,2,4,6

    float acc[4][4][4];
    #pragma unroll
    for (int mt = 0; mt < 4; mt++)
        #pragma unroll
        for (int nt = 0; nt < 4; nt++)
            #pragma unroll
            for (int r = 0; r < 4; r++) acc[mt][nt][r] = 0.f;

    uint4 st[8];
    stage_load(st, Ah, Al, Bh, Bl, bm, bn, 0, tid);

    const int nchunks = GK_ / BK_;   // 32
    for (int c = 0; c < nchunks; c++) {
        __syncthreads();   // previous compute done reading smem
        // store staged regs -> smem
        #pragma unroll
        for (int u = 0; u < 8; u++) {
            int id = tid + (u << 8);
            int tile = id >> 9;
            int rem = id & 511;
            int row = rem >> 2;
            int seg = rem & 3;
            *(uint4*)&smem[tile * TILE_ELEMS_ + row * ASTR_ + seg * 8] = st[u];
        }
        __syncthreads();
        // prefetch next chunk (LDG latency hides under the MMA block)
        if (c + 1 < nchunks)
            stage_load(st, Ah, Al, Bh, Bl, bm, bn, (c + 1) * BK_, tid);

        // compute: 2 k16 steps
        #pragma unroll
        for (int kk = 0; kk < 2; kk++) {
            int kcol = kk * 16 + tg2;
            uint32_t ahf[4][4], alf[4][4], bhf[4][2], blf[4][2];
            #pragma unroll
            for (int mt = 0; mt < 4; mt++) {
                int r0 = (warp_m * 64 + mt * 16 + g) * ASTR_ + kcol;
                const __nv_bfloat16* pH = smem;                 // Ah tile
                const __nv_bfloat16* pL = smem + TILE_ELEMS_;   // Al tile
                ahf[mt][0] = *(const uint32_t*)&pH[r0];
                ahf[mt][1] = *(const uint32_t*)&pH[r0 + 8 * ASTR_];
                ahf[mt][2] = *(const uint32_t*)&pH[r0 + 8];
                ahf[mt][3] = *(const uint32_t*)&pH[r0 + 8 * ASTR_ + 8];
                alf[mt][0] = *(const uint32_t*)&pL[r0];
                alf[mt][1] = *(const uint32_t*)&pL[r0 + 8 * ASTR_];
                alf[mt][2] = *(const uint32_t*)&pL[r0 + 8];
                alf[mt][3] = *(const uint32_t*)&pL[r0 + 8 * ASTR_ + 8];
            }
            #pragma unroll
            for (int nt = 0; nt < 4; nt++) {
                int rb = (warp_n * 32 + nt * 8 + g) * ASTR_ + kcol;
                const __nv_bfloat16* pH = smem + 2 * TILE_ELEMS_;  // Bh
                const __nv_bfloat16* pL = smem + 3 * TILE_ELEMS_;  // Bl
                bhf[nt][0] = *(const uint32_t*)&pH[rb];
                bhf[nt][1] = *(const uint32_t*)&pH[rb + 8];
                blf[nt][0] = *(const uint32_t*)&pL[rb];
                blf[nt][1] = *(const uint32_t*)&pL[rb + 8];
            }
            #pragma unroll
            for (int mt = 0; mt < 4; mt++)
                #pragma unroll
                for (int nt = 0; nt < 4; nt++) {
                    MMA16816(acc[mt][nt], ahf[mt], bhf[nt]);
                    MMA16816(acc[mt][nt], ahf[mt], blf[nt]);
                    MMA16816(acc[mt][nt], alf[mt], bhf[nt]);
                }
        }
    }

    // epilogue: direct fp32 stores
    #pragma unroll
    for (int mt = 0; mt < 4; mt++) {
        int m = bm + warp_m * 64 + mt * 16 + g;
        #pragma unroll
        for (int nt = 0; nt < 4; nt++) {
            int n = bn + warp_n * 32 + nt * 8 + tg2;
            *(float2*)&C[(size_t)m * N + n] =
                make_float2(acc[mt][nt][0], acc[mt][nt][1]);
            *(float2*)&C[(size_t)(m + 8) * N + n] =
                make_float2(acc[mt][nt][2], acc[mt][nt][3]);
        }
    }
}

// ---------------------------------------------------------------------------
// Flash attention, fp32 (unchanged — next round's target for mma.sync)
// ---------------------------------------------------------------------------
#define AST 68
#define ATTN_SMEM (3 * 64 * AST * 4)

__global__ __launch_bounds__(256)
void attn_k() {
    extern __shared__ float smf[];
    float* sQ = smf;
    float* sK = smf + 64 * AST;
    float* sV = smf + 2 * 64 * AST;

    int b = blockIdx.z, h = blockIdx.y, qt = blockIdx.x;
    int tid = threadIdx.x;
    int tx = tid & 15, ty = tid >> 4;
    int q0 = qt << 6;

    const float* qbase = g_qkv + (size_t)(b * S_) * TD_ + h * DK_;
    const float* kbase = qbase + D_;
    const float* vbase = qbase + 2 * D_;

    {
        int d = tid & 63;
        int r0 = (tid >> 6) << 2;
        #pragma unroll
        for (int p = 0; p < 4; p++) {
            int r = p * 16 + r0;
            float v0 = qbase[(size_t)(q0 + r + 0) * TD_ + d];
            float v1 = qbase[(size_t)(q0 + r + 1) * TD_ + d];
            float v2 = qbase[(size_t)(q0 + r + 2) * TD_ + d];
            float v3 = qbase[(size_t)(q0 + r + 3) * TD_ + d];
            *(float4*)&sQ[d * AST + r] = make_float4(v0, v1, v2, v3);
        }
    }

    float o[4][4] = {{0.f}};
    float m_i[4], l_i[4];
    #pragma unroll
    for (int i = 0; i < 4; i++) { m_i[i] = -INFINITY; l_i[i] = 0.f; }

    for (int kt = 0; kt <= qt; kt++) {
        int k0 = kt << 6;
        __syncthreads();
        {
            int d = tid & 63;
            int c0 = (tid >> 6) << 2;
            #pragma unroll
            for (int p = 0; p < 4; p++) {
                int c = p * 16 + c0;
                float v0 = kbase[(size_t)(k0 + c + 0) * TD_ + d];
                float v1 = kbase[(size_t)(k0 + c + 1) * TD_ + d];
                float v2 = kbase[(size_t)(k0 + c + 2) * TD_ + d];
                float v3 = kbase[(size_t)(k0 + c + 3) * TD_ + d];
                *(float4*)&sK[d * AST + c] = make_float4(v0, v1, v2, v3);
            }
        }
        {
            int f4 = (tid & 15) << 2;
            int rr = tid >> 4;
            #pragma unroll
            for (int p = 0; p < 4; p++) {
                int c = p * 16 + rr;
                float4 v = *(const float4*)&vbase[(size_t)(k0 + c) * TD_ + f4];
                *(float4*)&sV[c * AST + f4] = v;
            }
        }
        __syncthreads();

        float s[4][4] = {{0.f}};
        #pragma unroll 16
        for (int d = 0; d < 64; d++) {
            float4 qf = *(const float4*)&sQ[d * AST + (ty << 2)];
            float4 kf = *(const float4*)&sK[d * AST + (tx << 2)];
            float qa[4] = {qf.x, qf.y, qf.z, qf.w};
            float ka[4] = {kf.x, kf.y, kf.z, kf.w};
            #pragma unroll
            for (int i = 0; i < 4; i++)
                #pragma unroll
                for (int j = 0; j < 4; j++)
                    s[i][j] += qa[i] * ka[j];
        }

        const float sc = 0.125f;
        if (kt == qt) {
            #pragma unroll
            for (int i = 0; i < 4; i++)
                #pragma unroll
                for (int j = 0; j < 4; j++) {
                    int cc = (tx << 2) + j, rr = (ty << 2) + i;
                    s[i][j] = (cc <= rr) ? s[i][j] * sc : -INFINITY;
                }
        } else {
            #pragma unroll
            for (int i = 0; i < 4; i++)
                #pragma unroll
                for (int j = 0; j < 4; j++) s[i][j] *= sc;
        }

        #pragma unroll
        for (int i = 0; i < 4; i++) {
            float rmax = fmaxf(fmaxf(s[i][0], s[i][1]), fmaxf(s[i][2], s[i][3]));
            rmax = fmaxf(rmax, __shfl_xor_sync(0xffffffffu, rmax, 1));
            rmax = fmaxf(rmax, __shfl_xor_sync(0xffffffffu, rmax, 2));
            rmax = fmaxf(rmax, __shfl_xor_sync(0xffffffffu, rmax, 4));
            rmax = fmaxf(rmax, __shfl_xor_sync(0xffffffffu, rmax, 8));
            float nm = fmaxf(m_i[i], rmax);
            float corr = __expf(m_i[i] - nm);
            float ps = 0.f;
            #pragma unroll
            for (int j = 0; j < 4; j++) {
                float p = __expf(s[i][j] - nm);
                s[i][j] = p;
                ps += p;
            }
            ps += __shfl_xor_sync(0xffffffffu, ps, 1);
            ps += __shfl_xor_sync(0xffffffffu, ps, 2);
            ps += __shfl_xor_sync(0xffffffffu, ps, 4);
            ps += __shfl_xor_sync(0xffffffffu, ps, 8);
            l_i[i] = l_i[i] * corr + ps;
            m_i[i] = nm;
            #pragma unroll
            for (int j = 0; j < 4; j++) o[i][j] *= corr;
        }

        __syncthreads();
        #pragma unroll
        for (int j = 0; j < 4; j++) {
            *(float4*)&sK[((tx << 2) + j) * AST + (ty << 2)] =
                make_float4(s[0][j], s[1][j], s[2][j], s[3][j]);
        }
        __syncthreads();

        #pragma unroll 16
        for (int c = 0; c < 64; c++) {
            float4 pf = *(const float4*)&sK[c * AST + (ty << 2)];
            float4 vf = *(const float4*)&sV[c * AST + (tx << 2)];
            float pa[4] = {pf.x, pf.y, pf.z, pf.w};
            float va[4] = {vf.x, vf.y, vf.z, vf.w};
            #pragma unroll
            for (int i = 0; i < 4; i++)
                #pragma unroll
                for (int j = 0; j < 4; j++)
                    o[i][j] += pa[i] * va[j];
        }
    }

    float* obase = g_att + (size_t)(b * S_) * D_ + h * DK_;
    #pragma unroll
    for (int i = 0; i < 4; i++) {
        float inv = 1.0f / l_i[i];
        *(float4*)&obase[(size_t)(q0 + (ty << 2) + i) * D_ + (tx << 2)] =
            make_float4(o[i][0] * inv, o[i][1] * inv, o[i][2] * inv, o[i][3] * inv);
    }
}

// ---------------------------------------------------------------------------
extern "C" void kernel_launch(void* const* d_in, const int* in_sizes, int n_in,
                              void* d_out, int out_size) {
    const float* x    = (const float*)d_in[0];
    const float* Wqkv = (const float*)d_in[1];
    const float* Wo   = (const float*)d_in[2];
    float* out = (float*)d_out;

    float *qkv_p, *att_p;
    cudaGetSymbolAddress((void**)&qkv_p, g_qkv);
    cudaGetSymbolAddress((void**)&att_p, g_att);
    __nv_bfloat16 *xh, *xl, *wqh, *wql, *woh, *wol, *ath, *atl;
    cudaGetSymbolAddress((void**)&xh, g_xh);
    cudaGetSymbolAddress((void**)&xl, g_xl);
    cudaGetSymbolAddress((void**)&wqh, g_wqh);
    cudaGetSymbolAddress((void**)&wql, g_wql);
    cudaGetSymbolAddress((void**)&woh, g_woh);
    cudaGetSymbolAddress((void**)&wol, g_wol);
    cudaGetSymbolAddress((void**)&ath, g_ath);
    cudaGetSymbolAddress((void**)&atl, g_atl);

    cudaFuncSetAttribute(attn_k, cudaFuncAttributeMaxDynamicSharedMemorySize,
                         ATTN_SMEM);

    // 1. RoPE tables
    rope_table_k<<<(S_ * QUARTER_ + 255) / 256, 256>>>();
    // 2. split inputs to bf16 hi/lo
    split_k<<<(MROWS_ * D_ / 4 + 255) / 256, 256>>>(x, xh, xl, MROWS_ * D_ / 4);
    split_k<<<(TD_ * D_ / 4 + 255) / 256, 256>>>(Wqkv, wqh, wql, TD_ * D_ / 4);
    split_k<<<(D_ * D_ / 4 + 255) / 256, 256>>>(Wo, woh, wol, D_ * D_ / 4);
    // 3. QKV projection via mma.sync: [4096,1024] x [3072,1024]^T -> fp32
    gemm_mma<<<dim3(TD_ / 128, MROWS_ / 128), 256>>>(xh, xl, wqh, wql,
                                                     qkv_p, TD_);
    // 4. RoPE in place on q,k
    rope_apply_k<<<(B_ * S_ * 2 * H_ * QUARTER_ + 255) / 256, 256>>>();
    // 5. causal attention -> g_att [B,S,D]
    attn_k<<<dim3(S_ / 64, H_, B_), 256, ATTN_SMEM>>>();
    // 6. split attention output
    split_k<<<(MROWS_ * D_ / 4 + 255) / 256, 256>>>(att_p, ath, atl,
                                                    MROWS_ * D_ / 4);
    // 7. output projection via mma.sync -> d_out
    gemm_mma<<<dim3(D_ / 128, MROWS_ / 128), 256>>>(ath, atl, woh, wol,
                                                    out, D_);
}

// round 12
// speedup vs baseline: 1.9244x; 1.4654x over previous
#include <cuda_runtime.h>
#include <cuda_bf16.h>
#include <math.h>
#include <stdint.h>

#define B_ 2
#define S_ 2048
#define D_ 1024
#define H_ 16
#define DK_ 64
#define TD_ 3072          // 3*D
#define MROWS_ 4096       // B*S
#define QUARTER_ 16
#define GK_ 1024          // K dim of both projections

// ---------------------------------------------------------------------------
// Scratch (device globals — no allocation allowed)
// ---------------------------------------------------------------------------
__device__ float g_qkv[B_ * S_ * TD_];   // [B,S,3D] fp32 (QKV GEMM output)
__device__ float g_cos[S_ * QUARTER_];
__device__ float g_sin[S_ * QUARTER_];
// bf16 split-precision operand buffers for projections
__device__ __nv_bfloat16 g_xh[MROWS_ * D_],  g_xl[MROWS_ * D_];
__device__ __nv_bfloat16 g_wqh[TD_ * D_],    g_wql[TD_ * D_];
__device__ __nv_bfloat16 g_woh[D_ * D_],     g_wol[D_ * D_];
__device__ __nv_bfloat16 g_ath[MROWS_ * D_], g_atl[MROWS_ * D_];
// attention operands, [b,h,s,dk] layout, split hi/lo
#define QKVN_ (B_ * H_ * S_ * DK_)
__device__ __nv_bfloat16 g_qh[QKVN_], g_ql[QKVN_];
__device__ __nv_bfloat16 g_kh[QKVN_], g_kl[QKVN_];
__device__ __nv_bfloat16 g_vh[QKVN_], g_vl[QKVN_];

// ---------------------------------------------------------------------------
// small helpers
// ---------------------------------------------------------------------------
__device__ __forceinline__ uint32_t pk2(float a, float b) {
    __nv_bfloat162 t = __floats2bfloat162_rn(a, b);
    return *reinterpret_cast<uint32_t*>(&t);
}
__device__ __forceinline__ float lo_of(float v) {
    return v - __bfloat162float(__float2bfloat16(v));
}

#define MMA16816(d, a, b) \
    asm volatile( \
        "mma.sync.aligned.m16n8k16.row.col.f32.bf16.bf16.f32 " \
        "{%0,%1,%2,%3}, {%4,%5,%6,%7}, {%8,%9}, {%0,%1,%2,%3};" \
        : "+f"((d)[0]), "+f"((d)[1]), "+f"((d)[2]), "+f"((d)[3]) \
        : "r"((a)[0]), "r"((a)[1]), "r"((a)[2]), "r"((a)[3]), \
          "r"((b)[0]), "r"((b)[1]))

// ---------------------------------------------------------------------------
// RoPE tables
// ---------------------------------------------------------------------------
__global__ void rope_table_k() {
    int i = blockIdx.x * blockDim.x + threadIdx.x;
    if (i >= S_ * QUARTER_) return;
    int s = i / QUARTER_;
    int j = i % QUARTER_;
    double ang = pow(1.0e-4, (double)j / (double)(QUARTER_ - 1));
    double th = (double)s * ang;
    g_cos[i] = (float)cos(th);
    g_sin[i] = (float)sin(th);
}

// ---------------------------------------------------------------------------
// fp32 -> (bf16 hi, bf16 lo) splitter. 4 elements per thread.
// ---------------------------------------------------------------------------
__global__ __launch_bounds__(256)
void split_k(const float* __restrict__ src, __nv_bfloat16* __restrict__ hi,
             __nv_bfloat16* __restrict__ lo, int n4) {
    int i = blockIdx.x * blockDim.x + threadIdx.x;
    if (i >= n4) return;
    float4 v = ((const float4*)src)[i];
    ((uint32_t*)hi)[2 * i + 0] = pk2(v.x, v.y);
    ((uint32_t*)hi)[2 * i + 1] = pk2(v.z, v.w);
    ((uint32_t*)lo)[2 * i + 0] = pk2(lo_of(v.x), lo_of(v.y));
    ((uint32_t*)lo)[2 * i + 1] = pk2(lo_of(v.z), lo_of(v.w));
}

// ---------------------------------------------------------------------------
// prep: read g_qkv fp32, apply partial RoPE to q,k, split to bf16 hi/lo,
// write q/k/v in [b,h,s,dk] layout. One thread = 8 d-elements of one (b,h,s).
// ---------------------------------------------------------------------------
__device__ __forceinline__ void wr4(__nv_bfloat16* H, __nv_bfloat16* L,
                                    const float* v) {
    uint2 hh, ll;
    hh.x = pk2(v[0], v[1]); hh.y = pk2(v[2], v[3]);
    ll.x = pk2(lo_of(v[0]), lo_of(v[1]));
    ll.y = pk2(lo_of(v[2]), lo_of(v[3]));
    *(uint2*)H = hh;
    *(uint2*)L = ll;
}

__global__ __launch_bounds__(256)
void prep_k() {
    int idx = blockIdx.x * blockDim.x + threadIdx.x;
    if (idx >= B_ * H_ * S_ * 8) return;
    int t = idx & 7;
    int r = idx >> 3;
    int s = r & (S_ - 1); r >>= 11;
    int h = r & (H_ - 1);
    int b = r >> 4;
    int jj = (t < 4) ? (t << 2) : (16 + ((t - 4) << 2));
    size_t src = (size_t)(b * S_ + s) * TD_ + h * DK_;
    size_t dst = ((size_t)(b * H_ + h) * S_ + s) * DK_;

    float c[4], sn[4];
    bool dorope = jj < 16;
    if (dorope) {
        #pragma unroll
        for (int i = 0; i < 4; i++) {
            c[i]  = g_cos[s * QUARTER_ + jj + i];
            sn[i] = g_sin[s * QUARTER_ + jj + i];
        }
    }
    #pragma unroll
    for (int part = 0; part < 2; part++) {
        float4 x1 = *(const float4*)&g_qkv[src + part * D_ + jj];
        float4 x2 = *(const float4*)&g_qkv[src + part * D_ + jj + 32];
        float a[4] = {x1.x, x1.y, x1.z, x1.w};
        float bb[4] = {x2.x, x2.y, x2.z, x2.w};
        if (dorope) {
            #pragma unroll
            for (int i = 0; i < 4; i++) {
                float na = a[i] * c[i] - bb[i] * sn[i];
                float nb = a[i] * sn[i] + bb[i] * c[i];
                a[i] = na; bb[i] = nb;
            }
        }
        __nv_bfloat16* Hh = part ? g_kh : g_qh;
        __nv_bfloat16* Ll = part ? g_kl : g_ql;
        wr4(Hh + dst + jj, Ll + dst + jj, a);
        wr4(Hh + dst + jj + 32, Ll + dst + jj + 32, bb);
    }
    {
        float4 v1 = *(const float4*)&g_qkv[src + 2 * D_ + jj];
        float4 v2 = *(const float4*)&g_qkv[src + 2 * D_ + jj + 32];
        float a[4] = {v1.x, v1.y, v1.z, v1.w};
        float bb[4] = {v2.x, v2.y, v2.z, v2.w};
        wr4(g_vh + dst + jj, g_vl + dst + jj, a);
        wr4(g_vh + dst + jj + 32, g_vl + dst + jj + 32, bb);
    }
}

// ---------------------------------------------------------------------------
// mma.sync split-bf16 GEMM (round-6, known-good).
// ---------------------------------------------------------------------------
#define BK_ 32
#define ASTR_ 40
#define TILE_ELEMS_ (128 * ASTR_)

__device__ __forceinline__ void stage_load(
    uint4 st[8],
    const __nv_bfloat16* __restrict__ Ah, const __nv_bfloat16* __restrict__ Al,
    const __nv_bfloat16* __restrict__ Bh, const __nv_bfloat16* __restrict__ Bl,
    int bm, int bn, int kc, int tid) {
    #pragma unroll
    for (int u = 0; u < 8; u++) {
        int id = tid + (u << 8);
        int tile = id >> 9;
        int rem = id & 511;
        int row = rem >> 2;
        int seg = rem & 3;
        const __nv_bfloat16* src;
        if (tile == 0)      src = Ah + (size_t)(bm + row) * GK_;
        else if (tile == 1) src = Al + (size_t)(bm + row) * GK_;
        else if (tile == 2) src = Bh + (size_t)(bn + row) * GK_;
        else                src = Bl + (size_t)(bn + row) * GK_;
        st[u] = *(const uint4*)(src + kc + seg * 8);
    }
}

__global__ __launch_bounds__(256, 1)
void gemm_mma(const __nv_bfloat16* __restrict__ Ah, const __nv_bfloat16* __restrict__ Al,
              const __nv_bfloat16* __restrict__ Bh, const __nv_bfloat16* __restrict__ Bl,
              float* __restrict__ C, int N) {
    __shared__ __nv_bfloat16 smem[4 * TILE_ELEMS_];
    int tid = threadIdx.x;
    int lane = tid & 31, wid = tid >> 5;
    int warp_m = wid & 1;
    int warp_n = wid >> 1;
    int bm = blockIdx.y << 7, bn = blockIdx.x << 7;

    int g = lane >> 2;
    int tg2 = (lane & 3) << 1;

    float acc[4][4][4];
    #pragma unroll
    for (int mt = 0; mt < 4; mt++)
        #pragma unroll
        for (int nt = 0; nt < 4; nt++)
            #pragma unroll
            for (int r = 0; r < 4; r++) acc[mt][nt][r] = 0.f;

    uint4 st[8];
    stage_load(st, Ah, Al, Bh, Bl, bm, bn, 0, tid);

    const int nchunks = GK_ / BK_;
    for (int c = 0; c < nchunks; c++) {
        __syncthreads();
        #pragma unroll
        for (int u = 0; u < 8; u++) {
            int id = tid + (u << 8);
            int tile = id >> 9;
            int rem = id & 511;
            int row = rem >> 2;
            int seg = rem & 3;
            *(uint4*)&smem[tile * TILE_ELEMS_ + row * ASTR_ + seg * 8] = st[u];
        }
        __syncthreads();
        if (c + 1 < nchunks)
            stage_load(st, Ah, Al, Bh, Bl, bm, bn, (c + 1) * BK_, tid);

        #pragma unroll
        for (int kk = 0; kk < 2; kk++) {
            int kcol = kk * 16 + tg2;
            uint32_t ahf[4][4], alf[4][4], bhf[4][2], blf[4][2];
            #pragma unroll
            for (int mt = 0; mt < 4; mt++) {
                int r0 = (warp_m * 64 + mt * 16 + g) * ASTR_ + kcol;
                const __nv_bfloat16* pH = smem;
                const __nv_bfloat16* pL = smem + TILE_ELEMS_;
                ahf[mt][0] = *(const uint32_t*)&pH[r0];
                ahf[mt][1] = *(const uint32_t*)&pH[r0 + 8 * ASTR_];
                ahf[mt][2] = *(const uint32_t*)&pH[r0 + 8];
                ahf[mt][3] = *(const uint32_t*)&pH[r0 + 8 * ASTR_ + 8];
                alf[mt][0] = *(const uint32_t*)&pL[r0];
                alf[mt][1] = *(const uint32_t*)&pL[r0 + 8 * ASTR_];
                alf[mt][2] = *(const uint32_t*)&pL[r0 + 8];
                alf[mt][3] = *(const uint32_t*)&pL[r0 + 8 * ASTR_ + 8];
            }
            #pragma unroll
            for (int nt = 0; nt < 4; nt++) {
                int rb = (warp_n * 32 + nt * 8 + g) * ASTR_ + kcol;
                const __nv_bfloat16* pH = smem + 2 * TILE_ELEMS_;
                const __nv_bfloat16* pL = smem + 3 * TILE_ELEMS_;
                bhf[nt][0] = *(const uint32_t*)&pH[rb];
                bhf[nt][1] = *(const uint32_t*)&pH[rb + 8];
                blf[nt][0] = *(const uint32_t*)&pL[rb];
                blf[nt][1] = *(const uint32_t*)&pL[rb + 8];
            }
            #pragma unroll
            for (int mt = 0; mt < 4; mt++)
                #pragma unroll
                for (int nt = 0; nt < 4; nt++) {
                    MMA16816(acc[mt][nt], ahf[mt], bhf[nt]);
                    MMA16816(acc[mt][nt], ahf[mt], blf[nt]);
                    MMA16816(acc[mt][nt], alf[mt], bhf[nt]);
                }
        }
    }

    #pragma unroll
    for (int mt = 0; mt < 4; mt++) {
        int m = bm + warp_m * 64 + mt * 16 + g;
        #pragma unroll
        for (int nt = 0; nt < 4; nt++) {
            int n = bn + warp_n * 32 + nt * 8 + tg2;
            *(float2*)&C[(size_t)m * N + n] =
                make_float2(acc[mt][nt][0], acc[mt][nt][1]);
            *(float2*)&C[(size_t)(m + 8) * N + n] =
                make_float2(acc[mt][nt][2], acc[mt][nt][3]);
        }
    }
}

// ---------------------------------------------------------------------------
// Flash attention via mma.sync bf16 split precision.
// CTA: 128 q-rows for one (b,h). 8 warps, warp w owns rows 16w..16w+15.
// KV tiles of 64. Q frags hoisted to registers. V stored transposed in smem.
// P stays in registers (C-fragment -> A-fragment identity).
// ---------------------------------------------------------------------------
#define PADT_ 72
#define ATT_SMEM_ ((2 * 128 + 4 * 64) * PADT_ * 2)   // 73728 bytes

__global__ __launch_bounds__(256)
void attn_mma() {
    extern __shared__ __nv_bfloat16 smb[];
    __nv_bfloat16* sQh = smb;
    __nv_bfloat16* sQl = sQh + 128 * PADT_;
    __nv_bfloat16* sKh = sQl + 128 * PADT_;
    __nv_bfloat16* sKl = sKh + 64 * PADT_;
    __nv_bfloat16* sVh = sKl + 64 * PADT_;   // transposed: [d][key]
    __nv_bfloat16* sVl = sVh + 64 * PADT_;

    int tid = threadIdx.x;
    int lane = tid & 31, w = tid >> 5;
    int g = lane >> 2;             // fragment row group 0..7
    int q2 = (lane & 3) << 1;      // fragment col pair 0,2,4,6
    int b = blockIdx.z, h = blockIdx.y;
    int qt = (int)gridDim.x - 1 - (int)blockIdx.x;   // heavy tiles first
    int q0 = qt << 7;
    size_t base = ((size_t)(b * H_ + h)) * S_ * DK_;

    // ---- load Q tile (128 x 64) hi/lo into smem ----
    {
        int row = tid >> 1;
        int half = (tid & 1) << 2;
        const uint4* gh = (const uint4*)(g_qh + base + (size_t)(q0 + row) * DK_);
        const uint4* gl = (const uint4*)(g_ql + base + (size_t)(q0 + row) * DK_);
        uint4* dh = (uint4*)(sQh + row * PADT_);
        uint4* dl = (uint4*)(sQl + row * PADT_);
        #pragma unroll
        for (int u = 0; u < 4; u++) {
            dh[half + u] = gh[half + u];
            dl[half + u] = gl[half + u];
        }
    }
    __syncthreads();

    // ---- hoist Q fragments (all 4 k-steps), hi + lo ----
    uint32_t qfh[4][4], qfl[4][4];
    #pragma unroll
    for (int ks = 0; ks < 4; ks++) {
        int o = (w * 16 + g) * PADT_ + ks * 16 + q2;
        qfh[ks][0] = *(const uint32_t*)&sQh[o];
        qfh[ks][1] = *(const uint32_t*)&sQh[o + 8 * PADT_];
        qfh[ks][2] = *(const uint32_t*)&sQh[o + 8];
        qfh[ks][3] = *(const uint32_t*)&sQh[o + 8 * PADT_ + 8];
        qfl[ks][0] = *(const uint32_t*)&sQl[o];
        qfl[ks][1] = *(const uint32_t*)&sQl[o + 8 * PADT_];
        qfl[ks][2] = *(const uint32_t*)&sQl[o + 8];
        qfl[ks][3] = *(const uint32_t*)&sQl[o + 8 * PADT_ + 8];
    }

    float oacc[8][4];
    #pragma unroll
    for (int nt = 0; nt < 8; nt++)
        #pragma unroll
        for (int r = 0; r < 4; r++) oacc[nt][r] = 0.f;
    float m0 = -1e30f, m1 = -1e30f, l0 = 0.f, l1 = 0.f;
    int row0 = q0 + w * 16 + g, row1 = row0 + 8;

    int nkt = 2 * (qt + 1);
    for (int kt = 0; kt < nkt; kt++) {
        int k0 = kt << 6;
        __syncthreads();   // prior iteration done reading sK/sV
        // ---- K tile (64 x 64), row-major ----
        {
            int row = tid >> 2;
            int u = tid & 3;
            const uint4* gh = (const uint4*)(g_kh + base + (size_t)(k0 + row) * DK_);
            const uint4* gl = (const uint4*)(g_kl + base + (size_t)(k0 + row) * DK_);
            uint4* dh = (uint4*)(sKh + row * PADT_);
            uint4* dl = (uint4*)(sKl + row * PADT_);
            dh[u] = gh[u]; dh[u + 4] = gh[u + 4];
            dl[u] = gl[u]; dl[u + 4] = gl[u + 4];
        }
        // ---- V tile transposed: sVT[d][key]. warp = one key-octet, lane = d-pair
        {
            int dp = lane;           // d pair index 0..31
            int oct = w;             // key octet 0..7
            const __nv_bfloat16* gv = g_vh + base + (size_t)k0 * DK_;
            const __nv_bfloat16* gl = g_vl + base + (size_t)k0 * DK_;
            uint32_t r[8];
            #pragma unroll
            for (int i = 0; i < 8; i++)
                r[i] = *(const uint32_t*)(gv + (oct * 8 + i) * DK_ + dp * 2);
            uint4 lo4, hi4;
            lo4.x = __byte_perm(r[0], r[1], 0x5410); lo4.y = __byte_perm(r[2], r[3], 0x5410);
            lo4.z = __byte_perm(r[4], r[5], 0x5410); lo4.w = __byte_perm(r[6], r[7], 0x5410);
            hi4.x = __byte_perm(r[0], r[1], 0x7632); hi4.y = __byte_perm(r[2], r[3], 0x7632);
            hi4.z = __byte_perm(r[4], r[5], 0x7632); hi4.w = __byte_perm(r[6], r[7], 0x7632);
            *(uint4*)&sVh[(2 * dp) * PADT_ + oct * 8] = lo4;
            *(uint4*)&sVh[(2 * dp + 1) * PADT_ + oct * 8] = hi4;
            #pragma unroll
            for (int i = 0; i < 8; i++)
                r[i] = *(const uint32_t*)(gl + (oct * 8 + i) * DK_ + dp * 2);
            lo4.x = __byte_perm(r[0], r[1], 0x5410); lo4.y = __byte_perm(r[2], r[3], 0x5410);
            lo4.z = __byte_perm(r[4], r[5], 0x5410); lo4.w = __byte_perm(r[6], r[7], 0x5410);
            hi4.x = __byte_perm(r[0], r[1], 0x7632); hi4.y = __byte_perm(r[2], r[3], 0x7632);
            hi4.z = __byte_perm(r[4], r[5], 0x7632); hi4.w = __byte_perm(r[6], r[7], 0x7632);
            *(uint4*)&sVl[(2 * dp) * PADT_ + oct * 8] = lo4;
            *(uint4*)&sVl[(2 * dp + 1) * PADT_ + oct * 8] = hi4;
        }
        __syncthreads();

        // ---- S = Q K^T (3-term split) ----
        float sacc[8][4];
        #pragma unroll
        for (int nt = 0; nt < 8; nt++)
            #pragma unroll
            for (int r = 0; r < 4; r++) sacc[nt][r] = 0.f;

        #pragma unroll
        for (int ks = 0; ks < 4; ks++) {
            uint32_t kfh[8][2], kfl[8][2];
            #pragma unroll
            for (int nt = 0; nt < 8; nt++) {
                int o = (nt * 8 + g) * PADT_ + ks * 16 + q2;
                kfh[nt][0] = *(const uint32_t*)&sKh[o];
                kfh[nt][1] = *(const uint32_t*)&sKh[o + 8];
                kfl[nt][0] = *(const uint32_t*)&sKl[o];
                kfl[nt][1] = *(const uint32_t*)&sKl[o + 8];
            }
            #pragma unroll
            for (int nt = 0; nt < 8; nt++) {
                MMA16816(sacc[nt], qfh[ks], kfh[nt]);
                MMA16816(sacc[nt], qfh[ks], kfl[nt]);
                MMA16816(sacc[nt], qfl[ks], kfh[nt]);
            }
        }

        // ---- scale + causal mask ----
        const float sc = 0.125f;
        if (k0 + 63 > row0) {
            #pragma unroll
            for (int nt = 0; nt < 8; nt++) {
                int c0 = k0 + nt * 8 + q2, c1 = c0 + 1;
                sacc[nt][0] = (c0 <= row0) ? sacc[nt][0] * sc : -1e30f;
                sacc[nt][1] = (c1 <= row0) ? sacc[nt][1] * sc : -1e30f;
                sacc[nt][2] = (c0 <= row1) ? sacc[nt][2] * sc : -1e30f;
                sacc[nt][3] = (c1 <= row1) ? sacc[nt][3] * sc : -1e30f;
            }
        } else {
            #pragma unroll
            for (int nt = 0; nt < 8; nt++)
                #pragma unroll
                for (int r = 0; r < 4; r++) sacc[nt][r] *= sc;
        }

        // ---- online softmax (rows row0, row1; reduce over quad lanes) ----
        float rmax0 = -1e30f, rmax1 = -1e30f;
        #pragma unroll
        for (int nt = 0; nt < 8; nt++) {
            rmax0 = fmaxf(rmax0, fmaxf(sacc[nt][0], sacc[nt][1]));
            rmax1 = fmaxf(rmax1, fmaxf(sacc[nt][2], sacc[nt][3]));
        }
        rmax0 = fmaxf(rmax0, __shfl_xor_sync(0xffffffffu, rmax0, 1));
        rmax0 = fmaxf(rmax0, __shfl_xor_sync(0xffffffffu, rmax0, 2));
        rmax1 = fmaxf(rmax1, __shfl_xor_sync(0xffffffffu, rmax1, 1));
        rmax1 = fmaxf(rmax1, __shfl_xor_sync(0xffffffffu, rmax1, 2));
        float m0n = fmaxf(m0, rmax0), m1n = fmaxf(m1, rmax1);
        float corr0 = __expf(m0 - m0n), corr1 = __expf(m1 - m1n);
        float sum0 = 0.f, sum1 = 0.f;
        #pragma unroll
        for (int nt = 0; nt < 8; nt++) {
            sacc[nt][0] = __expf(sacc[nt][0] - m0n); sum0 += sacc[nt][0];
            sacc[nt][1] = __expf(sacc[nt][1] - m0n); sum0 += sacc[nt][1];
            sacc[nt][2] = __expf(sacc[nt][2] - m1n); sum1 += sacc[nt][2];
            sacc[nt][3] = __expf(sacc[nt][3] - m1n); sum1 += sacc[nt][3];
        }
        sum0 += __shfl_xor_sync(0xffffffffu, sum0, 1);
        sum0 += __shfl_xor_sync(0xffffffffu, sum0, 2);
        sum1 += __shfl_xor_sync(0xffffffffu, sum1, 1);
        sum1 += __shfl_xor_sync(0xffffffffu, sum1, 2);
        l0 = l0 * corr0 + sum0;  m0 = m0n;
        l1 = l1 * corr1 + sum1;  m1 = m1n;
        #pragma unroll
        for (int nt = 0; nt < 8; nt++) {
            oacc[nt][0] *= corr0; oacc[nt][1] *= corr0;
            oacc[nt][2] *= corr1; oacc[nt][3] *= corr1;
        }

        // ---- O += P V (P from registers; 3-term split) ----
        #pragma unroll
        for (int j = 0; j < 4; j++) {
            uint32_t ah[4], al[4];
            {
                float p0 = sacc[2 * j][0],     p1 = sacc[2 * j][1];
                float p2 = sacc[2 * j][2],     p3 = sacc[2 * j][3];
                float p4 = sacc[2 * j + 1][0], p5 = sacc[2 * j + 1][1];
                float p6 = sacc[2 * j + 1][2], p7 = sacc[2 * j + 1][3];
                ah[0] = pk2(p0, p1); ah[1] = pk2(p2, p3);
                ah[2] = pk2(p4, p5); ah[3] = pk2(p6, p7);
                al[0] = pk2(lo_of(p0), lo_of(p1)); al[1] = pk2(lo_of(p2), lo_of(p3));
                al[2] = pk2(lo_of(p4), lo_of(p5)); al[3] = pk2(lo_of(p6), lo_of(p7));
            }
            uint32_t vfh[8][2], vfl[8][2];
            #pragma unroll
            for (int nt = 0; nt < 8; nt++) {
                int o = (nt * 8 + g) * PADT_ + j * 16 + q2;
                vfh[nt][0] = *(const uint32_t*)&sVh[o];
                vfh[nt][1] = *(const uint32_t*)&sVh[o + 8];
                vfl[nt][0] = *(const uint32_t*)&sVl[o];
                vfl[nt][1] = *(const uint32_t*)&sVl[o + 8];
            }
            #pragma unroll
            for (int nt = 0; nt < 8; nt++) {
                MMA16816(oacc[nt], ah, vfh[nt]);
                MMA16816(oacc[nt], ah, vfl[nt]);
                MMA16816(oacc[nt], al, vfh[nt]);
            }
        }
    }

    // ---- epilogue: normalize, split to bf16 hi/lo, write [bs][D] layout ----
    float inv0 = 1.0f / l0, inv1 = 1.0f / l1;
    size_t ob0 = ((size_t)(b * S_ + row0)) * D_ + h * DK_;
    size_t ob1 = ((size_t)(b * S_ + row1)) * D_ + h * DK_;
    #pragma unroll
    for (int nt = 0; nt < 8; nt++) {
        int col = nt * 8 + q2;
        float e0 = oacc[nt][0] * inv0, e1 = oacc[nt][1] * inv0;
        float e2 = oacc[nt][2] * inv1, e3 = oacc[nt][3] * inv1;
        *(uint32_t*)&g_ath[ob0 + col] = pk2(e0, e1);
        *(uint32_t*)&g_atl[ob0 + col] = pk2(lo_of(e0), lo_of(e1));
        *(uint32_t*)&g_ath[ob1 + col] = pk2(e2, e3);
        *(uint32_t*)&g_atl[ob1 + col] = pk2(lo_of(e2), lo_of(e3));
    }
}

// ---------------------------------------------------------------------------
extern "C" void kernel_launch(void* const* d_in, const int* in_sizes, int n_in,
                              void* d_out, int out_size) {
    const float* x    = (const float*)d_in[0];
    const float* Wqkv = (const float*)d_in[1];
    const float* Wo   = (const float*)d_in[2];
    float* out = (float*)d_out;

    float* qkv_p;
    cudaGetSymbolAddress((void**)&qkv_p, g_qkv);
    __nv_bfloat16 *xh, *xl, *wqh, *wql, *woh, *wol, *ath, *atl;
    cudaGetSymbolAddress((void**)&xh, g_xh);
    cudaGetSymbolAddress((void**)&xl, g_xl);
    cudaGetSymbolAddress((void**)&wqh, g_wqh);
    cudaGetSymbolAddress((void**)&wql, g_wql);
    cudaGetSymbolAddress((void**)&woh, g_woh);
    cudaGetSymbolAddress((void**)&wol, g_wol);
    cudaGetSymbolAddress((void**)&ath, g_ath);
    cudaGetSymbolAddress((void**)&atl, g_atl);

    cudaFuncSetAttribute(attn_mma, cudaFuncAttributeMaxDynamicSharedMemorySize,
                         ATT_SMEM_);

    // 1. RoPE tables
    rope_table_k<<<(S_ * QUARTER_ + 255) / 256, 256>>>();
    // 2. split inputs to bf16 hi/lo
    split_k<<<(MROWS_ * D_ / 4 + 255) / 256, 256>>>(x, xh, xl, MROWS_ * D_ / 4);
    split_k<<<(TD_ * D_ / 4 + 255) / 256, 256>>>(Wqkv, wqh, wql, TD_ * D_ / 4);
    split_k<<<(D_ * D_ / 4 + 255) / 256, 256>>>(Wo, woh, wol, D_ * D_ / 4);
    // 3. QKV projection: [4096,1024] x [3072,1024]^T -> fp32
    gemm_mma<<<dim3(TD_ / 128, MROWS_ / 128), 256>>>(xh, xl, wqh, wql,
                                                     qkv_p, TD_);
    // 4. RoPE + split + [b,h,s,d] relayout of q,k,v
    prep_k<<<(B_ * H_ * S_ * 8 + 255) / 256, 256>>>();
    // 5. causal flash attention (tensor cores) -> split bf16 [bs][D]
    attn_mma<<<dim3(S_ / 128, H_, B_), 256, ATT_SMEM_>>>();
    // 6. output projection -> d_out
    gemm_mma<<<dim3(D_ / 128, MROWS_ / 128), 256>>>(ath, atl, woh, wol,
                                                    out, D_);
}

// round 14
// speedup vs baseline: 2.2113x; 1.1491x over previous
#include <cuda_runtime.h>
#include <cuda_bf16.h>
#include <math.h>
#include <stdint.h>

#define B_ 2
#define S_ 2048
#define D_ 1024
#define H_ 16
#define DK_ 64
#define TD_ 3072          // 3*D
#define MROWS_ 4096       // B*S
#define QUARTER_ 16
#define GK_ 1024          // K dim of both projections

// ---------------------------------------------------------------------------
// Scratch (device globals — no allocation allowed)
// ---------------------------------------------------------------------------
__device__ float g_qkv[B_ * S_ * TD_];   // [B,S,3D] fp32 (QKV GEMM output)
__device__ float g_cos[S_ * QUARTER_];
__device__ float g_sin[S_ * QUARTER_];
// bf16 split-precision operand buffers for projections
__device__ __nv_bfloat16 g_xh[MROWS_ * D_],  g_xl[MROWS_ * D_];
__device__ __nv_bfloat16 g_wqh[TD_ * D_],    g_wql[TD_ * D_];
__device__ __nv_bfloat16 g_woh[D_ * D_],     g_wol[D_ * D_];
__device__ __nv_bfloat16 g_ath[MROWS_ * D_], g_atl[MROWS_ * D_];
// attention operands, [b,h,s,dk] layout, split hi/lo
#define QKVN_ (B_ * H_ * S_ * DK_)
__device__ __nv_bfloat16 g_qh[QKVN_], g_ql[QKVN_];
__device__ __nv_bfloat16 g_kh[QKVN_], g_kl[QKVN_];
__device__ __nv_bfloat16 g_vh[QKVN_], g_vl[QKVN_];

// ---------------------------------------------------------------------------
// small helpers
// ---------------------------------------------------------------------------
__device__ __forceinline__ uint32_t pk2(float a, float b) {
    __nv_bfloat162 t = __floats2bfloat162_rn(a, b);
    return *reinterpret_cast<uint32_t*>(&t);
}
__device__ __forceinline__ float lo_of(float v) {
    return v - __bfloat162float(__float2bfloat16(v));
}
__device__ __forceinline__ uint32_t sm_u32(const void* p) {
    return (uint32_t)__cvta_generic_to_shared(p);
}

#define MMA16816(d, a, b) \
    asm volatile( \
        "mma.sync.aligned.m16n8k16.row.col.f32.bf16.bf16.f32 " \
        "{%0,%1,%2,%3}, {%4,%5,%6,%7}, {%8,%9}, {%0,%1,%2,%3};" \
        : "+f"((d)[0]), "+f"((d)[1]), "+f"((d)[2]), "+f"((d)[3]) \
        : "r"((a)[0]), "r"((a)[1]), "r"((a)[2]), "r"((a)[3]), \
          "r"((b)[0]), "r"((b)[1]))

#define LDSM4(r0, r1, r2, r3, addr) \
    asm volatile( \
        "ldmatrix.sync.aligned.m8n8.x4.shared.b16 {%0,%1,%2,%3}, [%4];" \
        : "=r"(r0), "=r"(r1), "=r"(r2), "=r"(r3) : "r"(addr))

// ---------------------------------------------------------------------------
// RoPE tables
// ---------------------------------------------------------------------------
__global__ void rope_table_k() {
    int i = blockIdx.x * blockDim.x + threadIdx.x;
    if (i >= S_ * QUARTER_) return;
    int s = i / QUARTER_;
    int j = i % QUARTER_;
    double ang = pow(1.0e-4, (double)j / (double)(QUARTER_ - 1));
    double th = (double)s * ang;
    g_cos[i] = (float)cos(th);
    g_sin[i] = (float)sin(th);
}

// ---------------------------------------------------------------------------
// fp32 -> (bf16 hi, bf16 lo) splitter. 4 elements per thread.
// ---------------------------------------------------------------------------
__global__ __launch_bounds__(256)
void split_k(const float* __restrict__ src, __nv_bfloat16* __restrict__ hi,
             __nv_bfloat16* __restrict__ lo, int n4) {
    int i = blockIdx.x * blockDim.x + threadIdx.x;
    if (i >= n4) return;
    float4 v = ((const float4*)src)[i];
    ((uint32_t*)hi)[2 * i + 0] = pk2(v.x, v.y);
    ((uint32_t*)hi)[2 * i + 1] = pk2(v.z, v.w);
    ((uint32_t*)lo)[2 * i + 0] = pk2(lo_of(v.x), lo_of(v.y));
    ((uint32_t*)lo)[2 * i + 1] = pk2(lo_of(v.z), lo_of(v.w));
}

// ---------------------------------------------------------------------------
// prep: read g_qkv fp32, apply partial RoPE to q,k, split to bf16 hi/lo,
// write q/k/v in [b,h,s,dk] layout.
// ---------------------------------------------------------------------------
__device__ __forceinline__ void wr4(__nv_bfloat16* H, __nv_bfloat16* L,
                                    const float* v) {
    uint2 hh, ll;
    hh.x = pk2(v[0], v[1]); hh.y = pk2(v[2], v[3]);
    ll.x = pk2(lo_of(v[0]), lo_of(v[1]));
    ll.y = pk2(lo_of(v[2]), lo_of(v[3]));
    *(uint2*)H = hh;
    *(uint2*)L = ll;
}

__global__ __launch_bounds__(256)
void prep_k() {
    int idx = blockIdx.x * blockDim.x + threadIdx.x;
    if (idx >= B_ * H_ * S_ * 8) return;
    int t = idx & 7;
    int r = idx >> 3;
    int s = r & (S_ - 1); r >>= 11;
    int h = r & (H_ - 1);
    int b = r >> 4;
    int jj = (t < 4) ? (t << 2) : (16 + ((t - 4) << 2));
    size_t src = (size_t)(b * S_ + s) * TD_ + h * DK_;
    size_t dst = ((size_t)(b * H_ + h) * S_ + s) * DK_;

    float c[4], sn[4];
    bool dorope = jj < 16;
    if (dorope) {
        #pragma unroll
        for (int i = 0; i < 4; i++) {
            c[i]  = g_cos[s * QUARTER_ + jj + i];
            sn[i] = g_sin[s * QUARTER_ + jj + i];
        }
    }
    #pragma unroll
    for (int part = 0; part < 2; part++) {
        float4 x1 = *(const float4*)&g_qkv[src + part * D_ + jj];
        float4 x2 = *(const float4*)&g_qkv[src + part * D_ + jj + 32];
        float a[4] = {x1.x, x1.y, x1.z, x1.w};
        float bb[4] = {x2.x, x2.y, x2.z, x2.w};
        if (dorope) {
            #pragma unroll
            for (int i = 0; i < 4; i++) {
                float na = a[i] * c[i] - bb[i] * sn[i];
                float nb = a[i] * sn[i] + bb[i] * c[i];
                a[i] = na; bb[i] = nb;
            }
        }
        __nv_bfloat16* Hh = part ? g_kh : g_qh;
        __nv_bfloat16* Ll = part ? g_kl : g_ql;
        wr4(Hh + dst + jj, Ll + dst + jj, a);
        wr4(Hh + dst + jj + 32, Ll + dst + jj + 32, bb);
    }
    {
        float4 v1 = *(const float4*)&g_qkv[src + 2 * D_ + jj];
        float4 v2 = *(const float4*)&g_qkv[src + 2 * D_ + jj + 32];
        float a[4] = {v1.x, v1.y, v1.z, v1.w};
        float bb[4] = {v2.x, v2.y, v2.z, v2.w};
        wr4(g_vh + dst + jj, g_vl + dst + jj, a);
        wr4(g_vh + dst + jj + 32, g_vl + dst + jj + 32, bb);
    }
}

// ---------------------------------------------------------------------------
// mma.sync split-bf16 GEMM with ldmatrix fragment loads.
// C[m][n] = sum_k (Ah+Al)[m][k] * (Bh+Bl)[n][k], dropping Al*Bl.
// CTA 128x128, BK=32, 8 warps (warp tile 64x32), fp32 accum.
// ---------------------------------------------------------------------------
#define BK_ 32
#define ASTR_ 40
#define TILE_ELEMS_ (128 * ASTR_)
#define TILE_B_ (TILE_ELEMS_ * 2)     // bytes per operand tile

__device__ __forceinline__ void stage_load(
    uint4 st[8],
    const __nv_bfloat16* __restrict__ Ah, const __nv_bfloat16* __restrict__ Al,
    const __nv_bfloat16* __restrict__ Bh, const __nv_bfloat16* __restrict__ Bl,
    int bm, int bn, int kc, int tid) {
    #pragma unroll
    for (int u = 0; u < 8; u++) {
        int id = tid + (u << 8);
        int tile = id >> 9;
        int rem = id & 511;
        int row = rem >> 2;
        int seg = rem & 3;
        const __nv_bfloat16* src;
        if (tile == 0)      src = Ah + (size_t)(bm + row) * GK_;
        else if (tile == 1) src = Al + (size_t)(bm + row) * GK_;
        else if (tile == 2) src = Bh + (size_t)(bn + row) * GK_;
        else                src = Bl + (size_t)(bn + row) * GK_;
        st[u] = *(const uint4*)(src + kc + seg * 8);
    }
}

__global__ __launch_bounds__(256, 1)
void gemm_mma(const __nv_bfloat16* __restrict__ Ah, const __nv_bfloat16* __restrict__ Al,
              const __nv_bfloat16* __restrict__ Bh, const __nv_bfloat16* __restrict__ Bl,
              float* __restrict__ C, int N) {
    __shared__ __nv_bfloat16 smem[4 * TILE_ELEMS_];
    int tid = threadIdx.x;
    int lane = tid & 31, wid = tid >> 5;
    int warp_m = wid & 1;
    int warp_n = wid >> 1;
    int bm = blockIdx.y << 7, bn = blockIdx.x << 7;

    int g = lane >> 2;
    int tg2 = (lane & 3) << 1;

    // ldmatrix per-lane address components
    uint32_t base_u = sm_u32(smem);
    int arow = ((lane >> 3) & 1) * 8 + (lane & 7);   // A: row within 16
    int acol = (lane >> 4) * 8;                      // A: k offset 0/8
    int brow = (lane >> 4) * 8 + (lane & 7);         // B: row within 16
    int bcol = ((lane >> 3) & 1) * 8;                // B: k offset 0/8
    uint32_t aAddr0 = base_u + ((warp_m * 64 + arow) * ASTR_ + acol) * 2;
    uint32_t bAddr0 = base_u + 2 * TILE_B_ +
                      ((warp_n * 32 + brow) * ASTR_ + bcol) * 2;

    float acc[4][4][4];
    #pragma unroll
    for (int mt = 0; mt < 4; mt++)
        #pragma unroll
        for (int nt = 0; nt < 4; nt++)
            #pragma unroll
            for (int r = 0; r < 4; r++) acc[mt][nt][r] = 0.f;

    uint4 st[8];
    stage_load(st, Ah, Al, Bh, Bl, bm, bn, 0, tid);

    const int nchunks = GK_ / BK_;
    for (int c = 0; c < nchunks; c++) {
        __syncthreads();
        #pragma unroll
        for (int u = 0; u < 8; u++) {
            int id = tid + (u << 8);
            int tile = id >> 9;
            int rem = id & 511;
            int row = rem >> 2;
            int seg = rem & 3;
            *(uint4*)&smem[tile * TILE_ELEMS_ + row * ASTR_ + seg * 8] = st[u];
        }
        __syncthreads();
        if (c + 1 < nchunks)
            stage_load(st, Ah, Al, Bh, Bl, bm, bn, (c + 1) * BK_, tid);

        #pragma unroll
        for (int kk = 0; kk < 2; kk++) {
            uint32_t koff = kk * 16 * 2;   // 16 bf16 = 32 bytes
            uint32_t ahf[4][4], alf[4][4], bhf[4][2], blf[4][2];
            #pragma unroll
            for (int mt = 0; mt < 4; mt++) {
                uint32_t a = aAddr0 + mt * (16 * ASTR_ * 2) + koff;
                LDSM4(ahf[mt][0], ahf[mt][1], ahf[mt][2], ahf[mt][3], a);
                LDSM4(alf[mt][0], alf[mt][1], alf[mt][2], alf[mt][3],
                      a + TILE_B_);
            }
            #pragma unroll
            for (int p = 0; p < 2; p++) {
                uint32_t bA = bAddr0 + p * (16 * ASTR_ * 2) + koff;
                LDSM4(bhf[2 * p][0], bhf[2 * p][1],
                      bhf[2 * p + 1][0], bhf[2 * p + 1][1], bA);
                LDSM4(blf[2 * p][0], blf[2 * p][1],
                      blf[2 * p + 1][0], blf[2 * p + 1][1], bA + TILE_B_);
            }
            #pragma unroll
            for (int mt = 0; mt < 4; mt++)
                #pragma unroll
                for (int nt = 0; nt < 4; nt++) {
                    MMA16816(acc[mt][nt], ahf[mt], bhf[nt]);
                    MMA16816(acc[mt][nt], ahf[mt], blf[nt]);
                    MMA16816(acc[mt][nt], alf[mt], bhf[nt]);
                }
        }
    }

    #pragma unroll
    for (int mt = 0; mt < 4; mt++) {
        int m = bm + warp_m * 64 + mt * 16 + g;
        #pragma unroll
        for (int nt = 0; nt < 4; nt++) {
            int n = bn + warp_n * 32 + nt * 8 + tg2;
            *(float2*)&C[(size_t)m * N + n] =
                make_float2(acc[mt][nt][0], acc[mt][nt][1]);
            *(float2*)&C[(size_t)(m + 8) * N + n] =
                make_float2(acc[mt][nt][2], acc[mt][nt][3]);
        }
    }
}

// ---------------------------------------------------------------------------
// Flash attention via mma.sync bf16 split precision + ldmatrix.
// CTA: 128 q-rows for one (b,h). 8 warps, warp w owns rows 16w..16w+15.
// ---------------------------------------------------------------------------
#define PADT_ 72
#define ATT_SMEM_ ((2 * 128 + 4 * 64) * PADT_ * 2)   // 73728 bytes

__global__ __launch_bounds__(256)
void attn_mma() {
    extern __shared__ __nv_bfloat16 smb[];
    __nv_bfloat16* sQh = smb;
    __nv_bfloat16* sQl = sQh + 128 * PADT_;
    __nv_bfloat16* sKh = sQl + 128 * PADT_;
    __nv_bfloat16* sKl = sKh + 64 * PADT_;
    __nv_bfloat16* sVh = sKl + 64 * PADT_;   // transposed: [d][key]
    __nv_bfloat16* sVl = sVh + 64 * PADT_;

    int tid = threadIdx.x;
    int lane = tid & 31, w = tid >> 5;
    int g = lane >> 2;             // fragment row group 0..7
    int q2 = (lane & 3) << 1;      // fragment col pair 0,2,4,6
    int b = blockIdx.z, h = blockIdx.y;
    int qt = (int)gridDim.x - 1 - (int)blockIdx.x;   // heavy tiles first
    int q0 = qt << 7;
    size_t base = ((size_t)(b * H_ + h)) * S_ * DK_;

    // ldmatrix per-lane address components for B-style frags (K and V)
    int brow = (lane >> 4) * 8 + (lane & 7);
    int bcol = ((lane >> 3) & 1) * 8;
    uint32_t sKh_u = sm_u32(sKh), sKl_u = sm_u32(sKl);
    uint32_t sVh_u = sm_u32(sVh), sVl_u = sm_u32(sVl);
    uint32_t kA0 = sKh_u + (brow * PADT_ + bcol) * 2;
    uint32_t kA0l = sKl_u + (brow * PADT_ + bcol) * 2;
    uint32_t vA0 = sVh_u + (brow * PADT_ + bcol) * 2;
    uint32_t vA0l = sVl_u + (brow * PADT_ + bcol) * 2;

    // ---- load Q tile (128 x 64) hi/lo into smem ----
    {
        int row = tid >> 1;
        int half = (tid & 1) << 2;
        const uint4* gh = (const uint4*)(g_qh + base + (size_t)(q0 + row) * DK_);
        const uint4* gl = (const uint4*)(g_ql + base + (size_t)(q0 + row) * DK_);
        uint4* dh = (uint4*)(sQh + row * PADT_);
        uint4* dl = (uint4*)(sQl + row * PADT_);
        #pragma unroll
        for (int u = 0; u < 4; u++) {
            dh[half + u] = gh[half + u];
            dl[half + u] = gl[half + u];
        }
    }
    __syncthreads();

    // ---- hoist Q fragments (all 4 k-steps), hi + lo, via ldmatrix ----
    uint32_t qfh[4][4], qfl[4][4];
    {
        int arow = ((lane >> 3) & 1) * 8 + (lane & 7);
        int acol = (lane >> 4) * 8;
        uint32_t qh_u = sm_u32(sQh) + ((w * 16 + arow) * PADT_ + acol) * 2;
        uint32_t ql_u = sm_u32(sQl) + ((w * 16 + arow) * PADT_ + acol) * 2;
        #pragma unroll
        for (int ks = 0; ks < 4; ks++) {
            LDSM4(qfh[ks][0], qfh[ks][1], qfh[ks][2], qfh[ks][3],
                  qh_u + ks * 32);
            LDSM4(qfl[ks][0], qfl[ks][1], qfl[ks][2], qfl[ks][3],
                  ql_u + ks * 32);
        }
    }

    float oacc[8][4];
    #pragma unroll
    for (int nt = 0; nt < 8; nt++)
        #pragma unroll
        for (int r = 0; r < 4; r++) oacc[nt][r] = 0.f;
    float m0 = -1e30f, m1 = -1e30f, l0 = 0.f, l1 = 0.f;
    int row0 = q0 + w * 16 + g, row1 = row0 + 8;

    int nkt = 2 * (qt + 1);
    for (int kt = 0; kt < nkt; kt++) {
        int k0 = kt << 6;
        __syncthreads();   // prior iteration done reading sK/sV
        // ---- K tile (64 x 64), row-major ----
        {
            int row = tid >> 2;
            int u = tid & 3;
            const uint4* gh = (const uint4*)(g_kh + base + (size_t)(k0 + row) * DK_);
            const uint4* gl = (const uint4*)(g_kl + base + (size_t)(k0 + row) * DK_);
            uint4* dh = (uint4*)(sKh + row * PADT_);
            uint4* dl = (uint4*)(sKl + row * PADT_);
            dh[u] = gh[u]; dh[u + 4] = gh[u + 4];
            dl[u] = gl[u]; dl[u + 4] = gl[u + 4];
        }
        // ---- V tile transposed: sVT[d][key] via byte_perm repack ----
        {
            int dp = lane;
            int oct = w;
            const __nv_bfloat16* gv = g_vh + base + (size_t)k0 * DK_;
            const __nv_bfloat16* gl = g_vl + base + (size_t)k0 * DK_;
            uint32_t r[8];
            #pragma unroll
            for (int i = 0; i < 8; i++)
                r[i] = *(const uint32_t*)(gv + (oct * 8 + i) * DK_ + dp * 2);
            uint4 lo4, hi4;
            lo4.x = __byte_perm(r[0], r[1], 0x5410); lo4.y = __byte_perm(r[2], r[3], 0x5410);
            lo4.z = __byte_perm(r[4], r[5], 0x5410); lo4.w = __byte_perm(r[6], r[7], 0x5410);
            hi4.x = __byte_perm(r[0], r[1], 0x7632); hi4.y = __byte_perm(r[2], r[3], 0x7632);
            hi4.z = __byte_perm(r[4], r[5], 0x7632); hi4.w = __byte_perm(r[6], r[7], 0x7632);
            *(uint4*)&sVh[(2 * dp) * PADT_ + oct * 8] = lo4;
            *(uint4*)&sVh[(2 * dp + 1) * PADT_ + oct * 8] = hi4;
            #pragma unroll
            for (int i = 0; i < 8; i++)
                r[i] = *(const uint32_t*)(gl + (oct * 8 + i) * DK_ + dp * 2);
            lo4.x = __byte_perm(r[0], r[1], 0x5410); lo4.y = __byte_perm(r[2], r[3], 0x5410);
            lo4.z = __byte_perm(r[4], r[5], 0x5410); lo4.w = __byte_perm(r[6], r[7], 0x5410);
            hi4.x = __byte_perm(r[0], r[1], 0x7632); hi4.y = __byte_perm(r[2], r[3], 0x7632);
            hi4.z = __byte_perm(r[4], r[5], 0x7632); hi4.w = __byte_perm(r[6], r[7], 0x7632);
            *(uint4*)&sVl[(2 * dp) * PADT_ + oct * 8] = lo4;
            *(uint4*)&sVl[(2 * dp + 1) * PADT_ + oct * 8] = hi4;
        }
        __syncthreads();

        // ---- S = Q K^T (3-term split) ----
        float sacc[8][4];
        #pragma unroll
        for (int nt = 0; nt < 8; nt++)
            #pragma unroll
            for (int r = 0; r < 4; r++) sacc[nt][r] = 0.f;

        #pragma unroll
        for (int ks = 0; ks < 4; ks++) {
            uint32_t kfh[8][2], kfl[8][2];
            #pragma unroll
            for (int p = 0; p < 4; p++) {
                uint32_t a = kA0 + (p * 16 * PADT_ + ks * 16) * 2;
                uint32_t al = kA0l + (p * 16 * PADT_ + ks * 16) * 2;
                LDSM4(kfh[2 * p][0], kfh[2 * p][1],
                      kfh[2 * p + 1][0], kfh[2 * p + 1][1], a);
                LDSM4(kfl[2 * p][0], kfl[2 * p][1],
                      kfl[2 * p + 1][0], kfl[2 * p + 1][1], al);
            }
            #pragma unroll
            for (int nt = 0; nt < 8; nt++) {
                MMA16816(sacc[nt], qfh[ks], kfh[nt]);
                MMA16816(sacc[nt], qfh[ks], kfl[nt]);
                MMA16816(sacc[nt], qfl[ks], kfh[nt]);
            }
        }

        // ---- scale + causal mask ----
        const float sc = 0.125f;
        if (k0 + 63 > row0) {
            #pragma unroll
            for (int nt = 0; nt < 8; nt++) {
                int c0 = k0 + nt * 8 + q2, c1 = c0 + 1;
                sacc[nt][0] = (c0 <= row0) ? sacc[nt][0] * sc : -1e30f;
                sacc[nt][1] = (c1 <= row0) ? sacc[nt][1] * sc : -1e30f;
                sacc[nt][2] = (c0 <= row1) ? sacc[nt][2] * sc : -1e30f;
                sacc[nt][3] = (c1 <= row1) ? sacc[nt][3] * sc : -1e30f;
            }
        } else {
            #pragma unroll
            for (int nt = 0; nt < 8; nt++)
                #pragma unroll
                for (int r = 0; r < 4; r++) sacc[nt][r] *= sc;
        }

        // ---- online softmax ----
        float rmax0 = -1e30f, rmax1 = -1e30f;
        #pragma unroll
        for (int nt = 0; nt < 8; nt++) {
            rmax0 = fmaxf(rmax0, fmaxf(sacc[nt][0], sacc[nt][1]));
            rmax1 = fmaxf(rmax1, fmaxf(sacc[nt][2], sacc[nt][3]));
        }
        rmax0 = fmaxf(rmax0, __shfl_xor_sync(0xffffffffu, rmax0, 1));
        rmax0 = fmaxf(rmax0, __shfl_xor_sync(0xffffffffu, rmax0, 2));
        rmax1 = fmaxf(rmax1, __shfl_xor_sync(0xffffffffu, rmax1, 1));
        rmax1 = fmaxf(rmax1, __shfl_xor_sync(0xffffffffu, rmax1, 2));
        float m0n = fmaxf(m0, rmax0), m1n = fmaxf(m1, rmax1);
        float corr0 = __expf(m0 - m0n), corr1 = __expf(m1 - m1n);
        float sum0 = 0.f, sum1 = 0.f;
        #pragma unroll
        for (int nt = 0; nt < 8; nt++) {
            sacc[nt][0] = __expf(sacc[nt][0] - m0n); sum0 += sacc[nt][0];
            sacc[nt][1] = __expf(sacc[nt][1] - m0n); sum0 += sacc[nt][1];
            sacc[nt][2] = __expf(sacc[nt][2] - m1n); sum1 += sacc[nt][2];
            sacc[nt][3] = __expf(sacc[nt][3] - m1n); sum1 += sacc[nt][3];
        }
        sum0 += __shfl_xor_sync(0xffffffffu, sum0, 1);
        sum0 += __shfl_xor_sync(0xffffffffu, sum0, 2);
        sum1 += __shfl_xor_sync(0xffffffffu, sum1, 1);
        sum1 += __shfl_xor_sync(0xffffffffu, sum1, 2);
        l0 = l0 * corr0 + sum0;  m0 = m0n;
        l1 = l1 * corr1 + sum1;  m1 = m1n;
        #pragma unroll
        for (int nt = 0; nt < 8; nt++) {
            oacc[nt][0] *= corr0; oacc[nt][1] *= corr0;
            oacc[nt][2] *= corr1; oacc[nt][3] *= corr1;
        }

        // ---- O += P V (P from registers; 3-term split) ----
        #pragma unroll
        for (int j = 0; j < 4; j++) {
            uint32_t ah[4], al[4];
            {
                float p0 = sacc[2 * j][0],     p1 = sacc[2 * j][1];
                float p2 = sacc[2 * j][2],     p3 = sacc[2 * j][3];
                float p4 = sacc[2 * j + 1][0], p5 = sacc[2 * j + 1][1];
                float p6 = sacc[2 * j + 1][2], p7 = sacc[2 * j + 1][3];
                ah[0] = pk2(p0, p1); ah[1] = pk2(p2, p3);
                ah[2] = pk2(p4, p5); ah[3] = pk2(p6, p7);
                al[0] = pk2(lo_of(p0), lo_of(p1)); al[1] = pk2(lo_of(p2), lo_of(p3));
                al[2] = pk2(lo_of(p4), lo_of(p5)); al[3] = pk2(lo_of(p6), lo_of(p7));
            }
            uint32_t vfh[8][2], vfl[8][2];
            #pragma unroll
            for (int p = 0; p < 4; p++) {
                uint32_t a = vA0 + (p * 16 * PADT_ + j * 16) * 2;
                uint32_t alo = vA0l + (p * 16 * PADT_ + j * 16) * 2;
                LDSM4(vfh[2 * p][0], vfh[2 * p][1],
                      vfh[2 * p + 1][0], vfh[2 * p + 1][1], a);
                LDSM4(vfl[2 * p][0], vfl[2 * p][1],
                      vfl[2 * p + 1][0], vfl[2 * p + 1][1], alo);
            }
            #pragma unroll
            for (int nt = 0; nt < 8; nt++) {
                MMA16816(oacc[nt], ah, vfh[nt]);
                MMA16816(oacc[nt], ah, vfl[nt]);
                MMA16816(oacc[nt], al, vfh[nt]);
            }
        }
    }

    // ---- epilogue: normalize, split to bf16 hi/lo, write [bs][D] layout ----
    float inv0 = 1.0f / l0, inv1 = 1.0f / l1;
    size_t ob0 = ((size_t)(b * S_ + row0)) * D_ + h * DK_;
    size_t ob1 = ((size_t)(b * S_ + row1)) * D_ + h * DK_;
    #pragma unroll
    for (int nt = 0; nt < 8; nt++) {
        int col = nt * 8 + q2;
        float e0 = oacc[nt][0] * inv0, e1 = oacc[nt][1] * inv0;
        float e2 = oacc[nt][2] * inv1, e3 = oacc[nt][3] * inv1;
        *(uint32_t*)&g_ath[ob0 + col] = pk2(e0, e1);
        *(uint32_t*)&g_atl[ob0 + col] = pk2(lo_of(e0), lo_of(e1));
        *(uint32_t*)&g_ath[ob1 + col] = pk2(e2, e3);
        *(uint32_t*)&g_atl[ob1 + col] = pk2(lo_of(e2), lo_of(e3));
    }
}

// ---------------------------------------------------------------------------
extern "C" void kernel_launch(void* const* d_in, const int* in_sizes, int n_in,
                              void* d_out, int out_size) {
    const float* x    = (const float*)d_in[0];
    const float* Wqkv = (const float*)d_in[1];
    const float* Wo   = (const float*)d_in[2];
    float* out = (float*)d_out;

    float* qkv_p;
    cudaGetSymbolAddress((void**)&qkv_p, g_qkv);
    __nv_bfloat16 *xh, *xl, *wqh, *wql, *woh, *wol, *ath, *atl;
    cudaGetSymbolAddress((void**)&xh, g_xh);
    cudaGetSymbolAddress((void**)&xl, g_xl);
    cudaGetSymbolAddress((void**)&wqh, g_wqh);
    cudaGetSymbolAddress((void**)&wql, g_wql);
    cudaGetSymbolAddress((void**)&woh, g_woh);
    cudaGetSymbolAddress((void**)&wol, g_wol);
    cudaGetSymbolAddress((void**)&ath, g_ath);
    cudaGetSymbolAddress((void**)&atl, g_atl);

    cudaFuncSetAttribute(attn_mma, cudaFuncAttributeMaxDynamicSharedMemorySize,
                         ATT_SMEM_);

    // 1. RoPE tables
    rope_table_k<<<(S_ * QUARTER_ + 255) / 256, 256>>>();
    // 2. split inputs to bf16 hi/lo
    split_k<<<(MROWS_ * D_ / 4 + 255) / 256, 256>>>(x, xh, xl, MROWS_ * D_ / 4);
    split_k<<<(TD_ * D_ / 4 + 255) / 256, 256>>>(Wqkv, wqh, wql, TD_ * D_ / 4);
    split_k<<<(D_ * D_ / 4 + 255) / 256, 256>>>(Wo, woh, wol, D_ * D_ / 4);
    // 3. QKV projection: [4096,1024] x [3072,1024]^T -> fp32
    gemm_mma<<<dim3(TD_ / 128, MROWS_ / 128), 256>>>(xh, xl, wqh, wql,
                                                     qkv_p, TD_);
    // 4. RoPE + split + [b,h,s,d] relayout of q,k,v
    prep_k<<<(B_ * H_ * S_ * 8 + 255) / 256, 256>>>();
    // 5. causal flash attention (tensor cores) -> split bf16 [bs][D]
    attn_mma<<<dim3(S_ / 128, H_, B_), 256, ATT_SMEM_>>>();
    // 6. output projection -> d_out
    gemm_mma<<<dim3(D_ / 128, MROWS_ / 128), 256>>>(ath, atl, woh, wol,
                                                    out, D_);
}